// round 2
// baseline (speedup 1.0000x reference)
#include <cuda_runtime.h>
#include <math.h>

#define N_    4096
#define E_    131072
#define FEAT_ 64
#define HID_  256
#define NEG_  (-1e9f)

// ---------------- scratch ----------------
__device__ float g_h0 [N_*HID_];
__device__ float g_x  [N_*HID_];
__device__ float g_hl [N_*HID_];
__device__ float g_xg [N_*HID_];
__device__ float g_sup[N_*2*HID_];
__device__ float g_q  [N_*HID_];
__device__ float g_k  [N_*HID_];
__device__ float g_v  [N_*HID_];
__device__ float g_hms[N_*HID_];
__device__ float g_S  [(size_t)N_*N_];
__device__ float g_el [N_*4];
__device__ float g_er [N_*4];
__device__ float g_y  [N_];
__device__ float g_xyz0[N_*3];
__device__ float g_xyz1[N_*3];
__device__ float g_xs[N_], g_ys[N_], g_zs[N_];
__device__ int   g_cnt[N_];
__device__ int   g_rowptr[N_+1];
__device__ int   g_cur[N_];
__device__ int   g_psrc[E_];
__device__ int   g_maskmode;

// ---------------- f32x2 helpers ----------------
typedef unsigned long long u64;

__device__ __forceinline__ u64 pack2(float a) {
    u64 r;
    asm("mov.b64 %0, {%1, %1};" : "=l"(r) : "f"(a));
    return r;
}
__device__ __forceinline__ void fma2(u64& c, u64 a, u64 b) {
    asm("fma.rn.f32x2 %0, %1, %2, %0;" : "+l"(c) : "l"(a), "l"(b));
}
__device__ __forceinline__ float2 up2(u64 v) {
    float2 f;
    asm("mov.b64 {%0, %1}, %2;" : "=f"(f.x), "=f"(f.y) : "l"(v));
    return f;
}

// ---------------- mask handling ----------------
__global__ void detect_mask_mode(const unsigned int* __restrict__ m) {
    bool allbin = true, anyfloat = false;
    for (int i = 0; i < 1024; i++) {
        unsigned int w = m[i];
        if (w == 0x3f800000u) anyfloat = true;
        if (w > 1u) allbin = false;
    }
    g_maskmode = anyfloat ? 2 : (allbin ? 1 : 0);
}
__device__ __forceinline__ bool mask_at(const void* p, size_t i, int mode) {
    if (mode == 0) return ((const unsigned char*)p)[i] != 0;
    if (mode == 1) return ((const int*)p)[i] != 0;
    return ((const float*)p)[i] != 0.0f;
}

// ================= 128x128x16 f32x2 SGEMM =================
// C[m,n] = epi( cacc*acc + bias[n] + c1*X1 + c2*X2 + c3*X3 ), optional relu, optional C2 copy.
// Requires M%128==0, N%128==0... N>=128 multiple of 128; K%16==0.
#define COMPUTE_TILE(ASB, BSB)                                                        \
    _Pragma("unroll")                                                                 \
    for (int kk = 0; kk < 16; kk++) {                                                 \
        float4 af0 = *(const float4*)&ASB[kk][ty8];                                   \
        float4 af1 = *(const float4*)&ASB[kk][ty8+4];                                 \
        ulonglong2 bb0 = *(const ulonglong2*)&BSB[kk][tx8];                           \
        ulonglong2 bb1 = *(const ulonglong2*)&BSB[kk][tx8+4];                         \
        u64 aa;                                                                       \
        aa=pack2(af0.x); fma2(acc[0][0],aa,bb0.x); fma2(acc[0][1],aa,bb0.y);          \
                         fma2(acc[0][2],aa,bb1.x); fma2(acc[0][3],aa,bb1.y);          \
        aa=pack2(af0.y); fma2(acc[1][0],aa,bb0.x); fma2(acc[1][1],aa,bb0.y);          \
                         fma2(acc[1][2],aa,bb1.x); fma2(acc[1][3],aa,bb1.y);          \
        aa=pack2(af0.z); fma2(acc[2][0],aa,bb0.x); fma2(acc[2][1],aa,bb0.y);          \
                         fma2(acc[2][2],aa,bb1.x); fma2(acc[2][3],aa,bb1.y);          \
        aa=pack2(af0.w); fma2(acc[3][0],aa,bb0.x); fma2(acc[3][1],aa,bb0.y);          \
                         fma2(acc[3][2],aa,bb1.x); fma2(acc[3][3],aa,bb1.y);          \
        aa=pack2(af1.x); fma2(acc[4][0],aa,bb0.x); fma2(acc[4][1],aa,bb0.y);          \
                         fma2(acc[4][2],aa,bb1.x); fma2(acc[4][3],aa,bb1.y);          \
        aa=pack2(af1.y); fma2(acc[5][0],aa,bb0.x); fma2(acc[5][1],aa,bb0.y);          \
                         fma2(acc[5][2],aa,bb1.x); fma2(acc[5][3],aa,bb1.y);          \
        aa=pack2(af1.z); fma2(acc[6][0],aa,bb0.x); fma2(acc[6][1],aa,bb0.y);          \
                         fma2(acc[6][2],aa,bb1.x); fma2(acc[6][3],aa,bb1.y);          \
        aa=pack2(af1.w); fma2(acc[7][0],aa,bb0.x); fma2(acc[7][1],aa,bb0.y);          \
                         fma2(acc[7][2],aa,bb1.x); fma2(acc[7][3],aa,bb1.y);          \
    }

__global__ __launch_bounds__(256) void sgemm128(
    const float* __restrict__ A, const float* __restrict__ B,
    float* __restrict__ C, float* __restrict__ C2,
    int M, int Nc, int K,
    const float* __restrict__ bias, int relu, float cacc,
    const float* __restrict__ X1, float c1,
    const float* __restrict__ X2, float c2,
    const float* __restrict__ X3, float c3)
{
    __shared__ __align__(16) float As[2][16][136];
    __shared__ __align__(16) float Bs[2][16][136];
    const int t = threadIdx.x;
    const int tx = t & 15, ty = t >> 4;
    const int tx8 = tx * 8, ty8 = ty * 8;
    const int m0 = blockIdx.y * 128, n0 = blockIdx.x * 128;
    const int ar = t >> 2, ak = (t & 3) * 4;
    const int br = t >> 5, bn = (t & 31) * 4;

    u64 acc[8][4] = {};

    float4 a0 = *(const float4*)&A[(size_t)(m0 + ar) * K + ak];
    float4 a1 = *(const float4*)&A[(size_t)(m0 + ar + 64) * K + ak];
    float4 b0 = *(const float4*)&B[(size_t)br * Nc + n0 + bn];
    float4 b1 = *(const float4*)&B[(size_t)(br + 8) * Nc + n0 + bn];
    As[0][ak+0][ar]=a0.x; As[0][ak+1][ar]=a0.y; As[0][ak+2][ar]=a0.z; As[0][ak+3][ar]=a0.w;
    As[0][ak+0][ar+64]=a1.x; As[0][ak+1][ar+64]=a1.y; As[0][ak+2][ar+64]=a1.z; As[0][ak+3][ar+64]=a1.w;
    *(float4*)&Bs[0][br][bn] = b0; *(float4*)&Bs[0][br+8][bn] = b1;
    __syncthreads();

    const int nt = K >> 4;
    for (int it = 0; it < nt; it++) {
        const int buf = it & 1;
        if (it + 1 < nt) {
            const int k0 = (it + 1) << 4;
            a0 = *(const float4*)&A[(size_t)(m0 + ar) * K + k0 + ak];
            a1 = *(const float4*)&A[(size_t)(m0 + ar + 64) * K + k0 + ak];
            b0 = *(const float4*)&B[(size_t)(k0 + br) * Nc + n0 + bn];
            b1 = *(const float4*)&B[(size_t)(k0 + br + 8) * Nc + n0 + bn];
        }
        if (buf == 0) { COMPUTE_TILE(As[0], Bs[0]) } else { COMPUTE_TILE(As[1], Bs[1]) }
        if (it + 1 < nt) {
            const int nb = buf ^ 1;
            As[nb][ak+0][ar]=a0.x; As[nb][ak+1][ar]=a0.y; As[nb][ak+2][ar]=a0.z; As[nb][ak+3][ar]=a0.w;
            As[nb][ak+0][ar+64]=a1.x; As[nb][ak+1][ar+64]=a1.y; As[nb][ak+2][ar+64]=a1.z; As[nb][ak+3][ar+64]=a1.w;
            *(float4*)&Bs[nb][br][bn] = b0; *(float4*)&Bs[nb][br+8][bn] = b1;
            __syncthreads();
        }
    }

#pragma unroll
    for (int i = 0; i < 8; i++) {
        const int m = m0 + ty8 + i;
        const size_t base = (size_t)m * Nc + n0 + tx8;
#pragma unroll
        for (int j2 = 0; j2 < 4; j2++) {
            float2 p = up2(acc[i][j2]);
#pragma unroll
            for (int e = 0; e < 2; e++) {
                const int n = n0 + tx8 + j2*2 + e;
                const size_t idx = base + j2*2 + e;
                float v = cacc * (e ? p.y : p.x);
                if (bias) v += bias[n];
                if (X1) v += c1 * X1[idx];
                if (X2) v += c2 * X2[idx];
                if (X3) v += c3 * X3[idx];
                if (relu) v = fmaxf(v, 0.0f);
                C[idx] = v;
                if (C2) C2[idx] = v;
            }
        }
    }
}

// ================= scores: S = mask ? (QK^T/16 - |dy|) : NEG =================
__global__ __launch_bounds__(256) void scores128(
    const float* __restrict__ Q, const float* __restrict__ Km,
    const float* __restrict__ xyz,
    const void* __restrict__ dmask, const void* __restrict__ bmask,
    float* __restrict__ S)
{
    __shared__ __align__(16) float As[2][16][136];
    __shared__ __align__(16) float Bs[2][16][136];
    __shared__ float xi[128][3], xj[128][3], sqi[128], sqj[128], yi[128], yj[128];
    const int t = threadIdx.x;
    const int tx = t & 15, ty = t >> 4;
    const int tx8 = tx * 8, ty8 = ty * 8;
    const int i0 = blockIdx.y * 128, j0 = blockIdx.x * 128;
    const int ar = t >> 2, ak = (t & 3) * 4;

    if (t < 128) {
        float a = xyz[(i0+t)*3+0], b = xyz[(i0+t)*3+1], c = xyz[(i0+t)*3+2];
        xi[t][0]=a; xi[t][1]=b; xi[t][2]=c;
        sqi[t] = fmaf(c,c,fmaf(b,b,a*a));
        yi[t]  = g_y[i0+t];
    } else {
        int u = t - 128;
        float a = xyz[(j0+u)*3+0], b = xyz[(j0+u)*3+1], c = xyz[(j0+u)*3+2];
        xj[u][0]=a; xj[u][1]=b; xj[u][2]=c;
        sqj[u] = fmaf(c,c,fmaf(b,b,a*a));
        yj[u]  = g_y[j0+u];
    }

    u64 acc[8][4] = {};

    float4 a0 = *(const float4*)&Q [(size_t)(i0 + ar) * HID_ + ak];
    float4 a1 = *(const float4*)&Q [(size_t)(i0 + ar + 64) * HID_ + ak];
    float4 b0 = *(const float4*)&Km[(size_t)(j0 + ar) * HID_ + ak];
    float4 b1 = *(const float4*)&Km[(size_t)(j0 + ar + 64) * HID_ + ak];
    As[0][ak+0][ar]=a0.x; As[0][ak+1][ar]=a0.y; As[0][ak+2][ar]=a0.z; As[0][ak+3][ar]=a0.w;
    As[0][ak+0][ar+64]=a1.x; As[0][ak+1][ar+64]=a1.y; As[0][ak+2][ar+64]=a1.z; As[0][ak+3][ar+64]=a1.w;
    Bs[0][ak+0][ar]=b0.x; Bs[0][ak+1][ar]=b0.y; Bs[0][ak+2][ar]=b0.z; Bs[0][ak+3][ar]=b0.w;
    Bs[0][ak+0][ar+64]=b1.x; Bs[0][ak+1][ar+64]=b1.y; Bs[0][ak+2][ar+64]=b1.z; Bs[0][ak+3][ar+64]=b1.w;
    __syncthreads();

    const int nt = HID_ >> 4;   // 16
    for (int it = 0; it < nt; it++) {
        const int buf = it & 1;
        if (it + 1 < nt) {
            const int k0 = (it + 1) << 4;
            a0 = *(const float4*)&Q [(size_t)(i0 + ar) * HID_ + k0 + ak];
            a1 = *(const float4*)&Q [(size_t)(i0 + ar + 64) * HID_ + k0 + ak];
            b0 = *(const float4*)&Km[(size_t)(j0 + ar) * HID_ + k0 + ak];
            b1 = *(const float4*)&Km[(size_t)(j0 + ar + 64) * HID_ + k0 + ak];
        }
        if (buf == 0) { COMPUTE_TILE(As[0], Bs[0]) } else { COMPUTE_TILE(As[1], Bs[1]) }
        if (it + 1 < nt) {
            const int nb = buf ^ 1;
            As[nb][ak+0][ar]=a0.x; As[nb][ak+1][ar]=a0.y; As[nb][ak+2][ar]=a0.z; As[nb][ak+3][ar]=a0.w;
            As[nb][ak+0][ar+64]=a1.x; As[nb][ak+1][ar+64]=a1.y; As[nb][ak+2][ar+64]=a1.z; As[nb][ak+3][ar+64]=a1.w;
            Bs[nb][ak+0][ar]=b0.x; Bs[nb][ak+1][ar]=b0.y; Bs[nb][ak+2][ar]=b0.z; Bs[nb][ak+3][ar]=b0.w;
            Bs[nb][ak+0][ar+64]=b1.x; Bs[nb][ak+1][ar+64]=b1.y; Bs[nb][ak+2][ar+64]=b1.z; Bs[nb][ak+3][ar+64]=b1.w;
            __syncthreads();
        }
    }

    const int mode = g_maskmode;
#pragma unroll
    for (int i = 0; i < 8; i++) {
        const int li = ty8 + i, gi = i0 + li;
        const float xa = xi[li][0], xb = xi[li][1], xc = xi[li][2];
        const float sqa = sqi[li], ya = yi[li];
        const size_t base = (size_t)gi * N_ + j0 + tx8;
#pragma unroll
        for (int j2 = 0; j2 < 4; j2++) {
            float2 p = up2(acc[i][j2]);
#pragma unroll
            for (int e = 0; e < 2; e++) {
                const int lj = tx8 + j2*2 + e;
                const size_t idx = base + j2*2 + e;
                float dot = fmaf(xc, xj[lj][2], fmaf(xb, xj[lj][1], xa * xj[lj][0]));
                float dist2 = (sqa + sqj[lj]) - 2.0f * dot;
                bool ok = mask_at(dmask, idx, mode) && mask_at(bmask, idx, mode) && (dist2 <= 100.0f);
                float av = e ? p.y : p.x;
                S[idx] = ok ? (av * 0.0625f - fabsf(ya - yj[lj])) : NEG_;
            }
        }
    }
}

// ================= softmax + attn@xyz fused =================
__global__ void softmax_xyz(float* __restrict__ S,
                            const float* __restrict__ xs, const float* __restrict__ ys,
                            const float* __restrict__ zs, float* __restrict__ out)
{
    __shared__ float r0[256], r1[256], r2[256];
    const int row = blockIdx.x, t = threadIdx.x;
    float* p = S + (size_t)row * N_;
    float4 v[4];
    float mx = -1e30f;
#pragma unroll
    for (int c = 0; c < 4; c++) {
        v[c] = *(float4*)&p[c*1024 + t*4];
        mx = fmaxf(mx, fmaxf(fmaxf(v[c].x, v[c].y), fmaxf(v[c].z, v[c].w)));
    }
    r0[t] = mx; __syncthreads();
    for (int s = 128; s > 0; s >>= 1) { if (t < s) r0[t] = fmaxf(r0[t], r0[t+s]); __syncthreads(); }
    mx = r0[0]; __syncthreads();
    float sum = 0.0f;
#pragma unroll
    for (int c = 0; c < 4; c++) {
        v[c].x = expf(v[c].x - mx); v[c].y = expf(v[c].y - mx);
        v[c].z = expf(v[c].z - mx); v[c].w = expf(v[c].w - mx);
        sum += v[c].x + v[c].y + v[c].z + v[c].w;
    }
    r0[t] = sum; __syncthreads();
    for (int s = 128; s > 0; s >>= 1) { if (t < s) r0[t] += r0[t+s]; __syncthreads(); }
    const float inv = 1.0f / r0[0];
    __syncthreads();
    float a0 = 0.f, a1 = 0.f, a2 = 0.f;
#pragma unroll
    for (int c = 0; c < 4; c++) {
        v[c].x *= inv; v[c].y *= inv; v[c].z *= inv; v[c].w *= inv;
        *(float4*)&p[c*1024 + t*4] = v[c];
        const int j = c*1024 + t*4;
        a0 = fmaf(v[c].x, xs[j], fmaf(v[c].y, xs[j+1], fmaf(v[c].z, xs[j+2], fmaf(v[c].w, xs[j+3], a0))));
        a1 = fmaf(v[c].x, ys[j], fmaf(v[c].y, ys[j+1], fmaf(v[c].z, ys[j+2], fmaf(v[c].w, ys[j+3], a1))));
        a2 = fmaf(v[c].x, zs[j], fmaf(v[c].y, zs[j+1], fmaf(v[c].z, zs[j+2], fmaf(v[c].w, zs[j+3], a2))));
    }
    r0[t]=a0; r1[t]=a1; r2[t]=a2; __syncthreads();
    for (int s = 128; s > 0; s >>= 1) {
        if (t < s) { r0[t]+=r0[t+s]; r1[t]+=r1[t+s]; r2[t]+=r2[t+s]; }
        __syncthreads();
    }
    if (t == 0) { out[row*3+0]=r0[0]; out[row*3+1]=r1[0]; out[row*3+2]=r2[0]; }
}

__global__ void xyz2soa(const float* __restrict__ xyz, float* __restrict__ xs,
                        float* __restrict__ ys, float* __restrict__ zs)
{
    int i = blockIdx.x * blockDim.x + threadIdx.x;
    if (i < N_) { xs[i] = xyz[3*i]; ys[i] = xyz[3*i+1]; zs[i] = xyz[3*i+2]; }
}

// ================= GAT pieces (unchanged) =================
__global__ void compute_elr(const float* __restrict__ hl, const float* __restrict__ al,
                            const float* __restrict__ ar)
{
    int idx = blockIdx.x * blockDim.x + threadIdx.x;
    if (idx >= N_*4) return;
    int node = idx >> 2, h = idx & 3;
    const float* row = hl + (size_t)node * HID_ + h * 64;
    float sl = 0.f, sr = 0.f;
#pragma unroll 8
    for (int d = 0; d < 64; d++) {
        float v = row[d];
        sl = fmaf(v, al[h*64+d], sl);
        sr = fmaf(v, ar[h*64+d], sr);
    }
    g_el[idx] = sl; g_er[idx] = sr;
}

__global__ void zero_cnt() { int i = blockIdx.x*blockDim.x + threadIdx.x; if (i < N_) g_cnt[i] = 0; }
__global__ void count_edges(const int* __restrict__ dst) {
    int e = blockIdx.x*blockDim.x + threadIdx.x; if (e < E_) atomicAdd(&g_cnt[dst[e]], 1);
}
__global__ void scan4096() {
    __shared__ int part[1024];
    int t = threadIdx.x, base = t * 4;
    int a0 = g_cnt[base], a1 = g_cnt[base+1], a2 = g_cnt[base+2], a3 = g_cnt[base+3];
    int s = a0 + a1 + a2 + a3;
    part[t] = s; __syncthreads();
    for (int off = 1; off < 1024; off <<= 1) {
        int v = (t >= off) ? part[t-off] : 0;
        __syncthreads();
        part[t] += v;
        __syncthreads();
    }
    int excl = part[t] - s;
    g_rowptr[base+0] = excl;           g_cur[base+0] = excl;
    g_rowptr[base+1] = excl+a0;        g_cur[base+1] = excl+a0;
    g_rowptr[base+2] = excl+a0+a1;     g_cur[base+2] = excl+a0+a1;
    g_rowptr[base+3] = excl+a0+a1+a2;  g_cur[base+3] = excl+a0+a1+a2;
    if (t == 1023) g_rowptr[4096] = part[1023];
}
__global__ void scatter_edges(const int* __restrict__ src, const int* __restrict__ dst) {
    int e = blockIdx.x*blockDim.x + threadIdx.x;
    if (e < E_) { int p = atomicAdd(&g_cur[dst[e]], 1); g_psrc[p] = src[e]; }
}

__global__ void gat_aggregate(const float* __restrict__ hl, float* __restrict__ xg)
{
    const int node = (blockIdx.x * blockDim.x + threadIdx.x) >> 5;
    const int lane = threadIdx.x & 31;
    if (node >= N_) return;
    const int beg = g_rowptr[node], end = g_rowptr[node+1];
    const float er_i = (lane < 4) ? g_er[node*4 + lane] : 0.f;
    float m = -1e30f;
    for (int p = beg; p < end; p++) {
        int s = g_psrc[p];
        if (lane < 4) {
            float v = g_el[s*4 + lane] + er_i;
            float e = (v > 0.f) ? v : 0.2f * v;
            m = fmaxf(m, e);
        }
    }
    float m0 = __shfl_sync(0xffffffffu, m, 0), m1 = __shfl_sync(0xffffffffu, m, 1);
    float m2 = __shfl_sync(0xffffffffu, m, 2), m3 = __shfl_sync(0xffffffffu, m, 3);
    const int myh = lane >> 3;
    float4 acc0 = {0,0,0,0}, acc1 = {0,0,0,0};
    float z = 0.f;
    for (int p = beg; p < end; p++) {
        int s = g_psrc[p];
        float w = 0.f;
        if (lane < 4) {
            float v = g_el[s*4 + lane] + er_i;
            float e = (v > 0.f) ? v : 0.2f * v;
            float mm = (lane==0)?m0:(lane==1)?m1:(lane==2)?m2:m3;
            w = expf(e - mm);
            z += w;
        }
        float w0 = __shfl_sync(0xffffffffu, w, 0), w1 = __shfl_sync(0xffffffffu, w, 1);
        float w2 = __shfl_sync(0xffffffffu, w, 2), w3 = __shfl_sync(0xffffffffu, w, 3);
        float wm = (myh==0)?w0:(myh==1)?w1:(myh==2)?w2:w3;
        const float4* hp = (const float4*)(hl + (size_t)s * HID_ + lane * 8);
        float4 hv0 = hp[0], hv1 = hp[1];
        acc0.x=fmaf(wm,hv0.x,acc0.x); acc0.y=fmaf(wm,hv0.y,acc0.y);
        acc0.z=fmaf(wm,hv0.z,acc0.z); acc0.w=fmaf(wm,hv0.w,acc0.w);
        acc1.x=fmaf(wm,hv1.x,acc1.x); acc1.y=fmaf(wm,hv1.y,acc1.y);
        acc1.z=fmaf(wm,hv1.z,acc1.z); acc1.w=fmaf(wm,hv1.w,acc1.w);
    }
    float z0 = __shfl_sync(0xffffffffu, z, 0), z1 = __shfl_sync(0xffffffffu, z, 1);
    float z2 = __shfl_sync(0xffffffffu, z, 2), z3 = __shfl_sync(0xffffffffu, z, 3);
    float zm = (myh==0)?z0:(myh==1)?z1:(myh==2)?z2:z3;
    float inv = 1.0f / (zm + 1e-9f);
    acc0.x*=inv; acc0.y*=inv; acc0.z*=inv; acc0.w*=inv;
    acc1.x*=inv; acc1.y*=inv; acc1.z*=inv; acc1.w*=inv;
    float4* op = (float4*)(xg + (size_t)node * HID_ + lane * 8);
    op[0] = acc0; op[1] = acc1;
}

__global__ void pack_support(const float* __restrict__ xg, const float* __restrict__ h0,
                             float* __restrict__ sup)
{
    int i = blockIdx.x * blockDim.x + threadIdx.x;
    if (i >= N_ * 512) return;
    int r = i >> 9, c = i & 511;
    sup[i] = (c < 256) ? xg[(size_t)r*256 + c] : h0[(size_t)r*256 + (c-256)];
}

__global__ void yhat_k(const float* __restrict__ x, const float* __restrict__ W,
                       const float* __restrict__ b)
{
    int i = blockIdx.x * blockDim.x + threadIdx.x;
    if (i >= N_) return;
    const float* r = x + (size_t)i * HID_;
    float l0 = b[0], l1 = b[1];
#pragma unroll 8
    for (int d = 0; d < HID_; d++) {
        float v = r[d];
        l0 = fmaf(v, W[2*d+0], l0);
        l1 = fmaf(v, W[2*d+1], l1);
    }
    g_y[i] = 1.0f / (1.0f + expf(l0 - l1));
}

__global__ void cls_k(const float* __restrict__ x, const float* __restrict__ W,
                      const float* __restrict__ b, float* __restrict__ out)
{
    int i = blockIdx.x * blockDim.x + threadIdx.x;
    if (i >= N_) return;
    const float* r = x + (size_t)i * HID_;
    float l0 = b[0], l1 = b[1];
#pragma unroll 8
    for (int d = 0; d < HID_; d++) {
        float v = r[d];
        l0 = fmaf(v, W[2*d+0], l0);
        l1 = fmaf(v, W[2*d+1], l1);
    }
    out[2*i+0] = l0;
    out[2*i+1] = l1;
}

// ================= host orchestration =================
extern "C" void kernel_launch(void* const* d_in, const int* in_sizes, int n_in,
                              void* d_out, int out_size)
{
    const float* feat   = (const float*)d_in[0];
    const float* xyz_in = (const float*)d_in[1];
    const int*   src    = (const int*)  d_in[2];
    const int*   dst    = (const int*)  d_in[3];
    const void*  dmask  = d_in[4];
    const void*  bmask  = d_in[5];
    const float* fcW  = (const float*)d_in[6];
    const float* fcb  = (const float*)d_in[7];
    const float* gatW = (const float*)d_in[8];
    const float* al   = (const float*)d_in[9];
    const float* ar   = (const float*)d_in[10];
    const float* gcW  = (const float*)d_in[11];
    const float* cgW  = (const float*)d_in[12];
    const float* cgb  = (const float*)d_in[13];
    const float* qW   = (const float*)d_in[14];
    const float* qb   = (const float*)d_in[15];
    const float* kW   = (const float*)d_in[16];
    const float* kb   = (const float*)d_in[17];
    const float* vW   = (const float*)d_in[18];
    const float* vb   = (const float*)d_in[19];
    const float* oW   = (const float*)d_in[20];
    const float* ob   = (const float*)d_in[21];
    const float* clsW = (const float*)d_in[22];
    const float* clsb = (const float*)d_in[23];

    float *px, *ph0, *phl, *pxg, *psup, *pq, *pk, *pv, *phms, *pS, *pxyz0, *pxyz1;
    float *pxs, *pys, *pzs;
    cudaGetSymbolAddress((void**)&px,    g_x);
    cudaGetSymbolAddress((void**)&ph0,   g_h0);
    cudaGetSymbolAddress((void**)&phl,   g_hl);
    cudaGetSymbolAddress((void**)&pxg,   g_xg);
    cudaGetSymbolAddress((void**)&psup,  g_sup);
    cudaGetSymbolAddress((void**)&pq,    g_q);
    cudaGetSymbolAddress((void**)&pk,    g_k);
    cudaGetSymbolAddress((void**)&pv,    g_v);
    cudaGetSymbolAddress((void**)&phms,  g_hms);
    cudaGetSymbolAddress((void**)&pS,    g_S);
    cudaGetSymbolAddress((void**)&pxyz0, g_xyz0);
    cudaGetSymbolAddress((void**)&pxyz1, g_xyz1);
    cudaGetSymbolAddress((void**)&pxs,   g_xs);
    cudaGetSymbolAddress((void**)&pys,   g_ys);
    cudaGetSymbolAddress((void**)&pzs,   g_zs);

    detect_mask_mode<<<1, 1>>>((const unsigned int*)dmask);

    // h = relu(feat @ fcW + fcb) -> x and h0
    sgemm128<<<dim3(HID_/128, N_/128), 256>>>(feat, fcW, px, ph0, N_, HID_, FEAT_,
                                              fcb, 1, 1.0f, nullptr,0.f, nullptr,0.f, nullptr,0.f);

    zero_cnt<<<N_/256, 256>>>();
    count_edges<<<E_/256, 256>>>(dst);
    scan4096<<<1, 1024>>>();
    scatter_edges<<<E_/256, 256>>>(src, dst);

    const float ALPHA = 0.1f, LAMDA = 0.5f;
    for (int l = 0; l < 4; l++) {
        sgemm128<<<dim3(HID_/128, N_/128), 256>>>(px, gatW + (size_t)l*HID_*HID_, phl, nullptr,
                                                  N_, HID_, HID_, nullptr, 0, 1.0f,
                                                  nullptr,0.f, nullptr,0.f, nullptr,0.f);
        compute_elr<<<(N_*4)/256, 256>>>(phl, al + l*4*64, ar + l*4*64);
        gat_aggregate<<<N_/8, 256>>>(phl, pxg);
        pack_support<<<(N_*512)/256, 256>>>(pxg, ph0, psup);
        float theta = fminf(1.0f, logf(LAMDA / (float)(l + 1) + 1.0f));
        sgemm128<<<dim3(HID_/128, N_/128), 256>>>(psup, gcW + (size_t)l*512*HID_, px, nullptr,
                                                  N_, HID_, 512, nullptr, 0, theta,
                                                  pxg, (1.0f-theta)*(1.0f-ALPHA),
                                                  ph0, (1.0f-theta)*ALPHA,
                                                  px,  1.0f);
    }

    yhat_k<<<N_/256, 256>>>(px, cgW, cgb);

    const float* xyz_cur = xyz_in;
    float* xyz_buf[2] = { pxyz0, pxyz1 };
    for (int l = 0; l < 4; l++) {
        sgemm128<<<dim3(HID_/128, N_/128), 256>>>(px, qW + (size_t)l*HID_*HID_, pq, nullptr,
                                                  N_, HID_, HID_, qb + l*HID_, 0, 1.0f,
                                                  nullptr,0.f, nullptr,0.f, nullptr,0.f);
        sgemm128<<<dim3(HID_/128, N_/128), 256>>>(px, kW + (size_t)l*HID_*HID_, pk, nullptr,
                                                  N_, HID_, HID_, kb + l*HID_, 0, 1.0f,
                                                  nullptr,0.f, nullptr,0.f, nullptr,0.f);
        sgemm128<<<dim3(HID_/128, N_/128), 256>>>(px, vW + (size_t)l*HID_*HID_, pv, nullptr,
                                                  N_, HID_, HID_, vb + l*HID_, 0, 1.0f,
                                                  nullptr,0.f, nullptr,0.f, nullptr,0.f);
        scores128<<<dim3(N_/128, N_/128), 256>>>(pq, pk, xyz_cur, dmask, bmask, pS);
        xyz2soa<<<N_/256, 256>>>(xyz_cur, pxs, pys, pzs);
        softmax_xyz<<<N_, 256>>>(pS, pxs, pys, pzs, xyz_buf[l & 1]);
        sgemm128<<<dim3(HID_/128, N_/128), 256>>>(pS, pv, phms, nullptr, N_, HID_, N_,
                                                  nullptr, 0, 1.0f,
                                                  nullptr,0.f, nullptr,0.f, nullptr,0.f);
        sgemm128<<<dim3(HID_/128, N_/128), 256>>>(phms, oW + (size_t)l*HID_*HID_, px, nullptr,
                                                  N_, HID_, HID_, ob + l*HID_, 0, 1.0f,
                                                  px, 1.0f, nullptr,0.f, nullptr,0.f);
        xyz_cur = xyz_buf[l & 1];
    }

    cls_k<<<N_/256, 256>>>(px, clsW, clsb, (float*)d_out);
}

// round 4
// speedup vs baseline: 1.2254x; 1.2254x over previous
#include <cuda_runtime.h>
#include <math.h>

#define N_    4096
#define E_    131072
#define FEAT_ 64
#define HID_  256
#define NEG_  (-1e9f)

// ---------------- scratch ----------------
__device__ float g_h0 [N_*HID_];
__device__ float g_x  [N_*HID_];
__device__ float g_hl [N_*HID_];
__device__ float g_xg [N_*HID_];
__device__ float g_sup[N_*2*HID_];
__device__ float g_q  [N_*HID_];
__device__ float g_k  [N_*HID_];
__device__ float g_v  [N_*HID_];
__device__ float g_hms[N_*HID_];
__device__ float g_S  [(size_t)N_*N_];
__device__ float g_el [N_*4];
__device__ float g_er [N_*4];
__device__ float g_y  [N_];
__device__ float g_xyz0[N_*3];
__device__ float g_xyz1[N_*3];
__device__ float g_xs[N_], g_ys[N_], g_zs[N_];
__device__ int   g_cnt[N_];
__device__ int   g_rowptr[N_+1];
__device__ int   g_cur[N_];
__device__ int   g_psrc[E_];
__device__ int   g_maskmode;

// ---------------- mask handling ----------------
__global__ void detect_mask_mode(const unsigned int* __restrict__ m) {
    bool allbin = true, anyfloat = false;
    for (int i = 0; i < 1024; i++) {
        unsigned int w = m[i];
        if (w == 0x3f800000u) anyfloat = true;
        if (w > 1u) allbin = false;
    }
    g_maskmode = anyfloat ? 2 : (allbin ? 1 : 0);
}
__device__ __forceinline__ bool mask_at(const void* p, size_t i, int mode) {
    if (mode == 0) return ((const unsigned char*)p)[i] != 0;
    if (mode == 1) return ((const int*)p)[i] != 0;
    return ((const float*)p)[i] != 0.0f;
}

// ---------------- 128x128x16 scalar SGEMM core ----------------
// 256 threads as 16x16; thread handles rows {ty4..+3, 64+ty4..+3} x cols {tx4..+3, 64+tx4..+3}.
#define KSTEP(ASB, BSB, kk)                                                     \
    do {                                                                        \
        float4 a0_ = *(const float4*)&ASB[kk][ty4];                             \
        float4 a1_ = *(const float4*)&ASB[kk][ty4 + 64];                        \
        float4 b0_ = *(const float4*)&BSB[kk][tx4];                             \
        float4 b1_ = *(const float4*)&BSB[kk][tx4 + 64];                        \
        const float ax_[8] = {a0_.x,a0_.y,a0_.z,a0_.w,a1_.x,a1_.y,a1_.z,a1_.w}; \
        const float bx_[8] = {b0_.x,b0_.y,b0_.z,b0_.w,b1_.x,b1_.y,b1_.z,b1_.w}; \
        _Pragma("unroll")                                                       \
        for (int i_ = 0; i_ < 8; i_++)                                          \
            _Pragma("unroll")                                                   \
            for (int j_ = 0; j_ < 8; j_++)                                      \
                acc[i_][j_] = fmaf(ax_[i_], bx_[j_], acc[i_][j_]);              \
    } while (0)

__global__ __launch_bounds__(256) void sgemm128(
    const float* __restrict__ A, const float* __restrict__ B,
    float* __restrict__ C, float* __restrict__ C2,
    int M, int Nc, int K,
    const float* __restrict__ bias, int relu, float cacc,
    const float* __restrict__ X1, float c1,
    const float* __restrict__ X2, float c2,
    const float* __restrict__ X3, float c3)
{
    __shared__ __align__(16) float As[2][16][132];
    __shared__ __align__(16) float Bs[2][16][132];
    const int t = threadIdx.x;
    const int tx = t & 15, ty = t >> 4;
    const int tx4 = tx * 4, ty4 = ty * 4;
    const int m0 = blockIdx.y * 128, n0 = blockIdx.x * 128;
    const int ar = t >> 2, ak = (t & 3) * 4;
    const int br = t >> 5, bn = (t & 31) * 4;

    float acc[8][8] = {};

    float4 pa0 = *(const float4*)&A[(size_t)(m0 + ar) * K + ak];
    float4 pa1 = *(const float4*)&A[(size_t)(m0 + ar + 64) * K + ak];
    float4 pb0 = *(const float4*)&B[(size_t)br * Nc + n0 + bn];
    float4 pb1 = *(const float4*)&B[(size_t)(br + 8) * Nc + n0 + bn];
    As[0][ak+0][ar]=pa0.x; As[0][ak+1][ar]=pa0.y; As[0][ak+2][ar]=pa0.z; As[0][ak+3][ar]=pa0.w;
    As[0][ak+0][ar+64]=pa1.x; As[0][ak+1][ar+64]=pa1.y; As[0][ak+2][ar+64]=pa1.z; As[0][ak+3][ar+64]=pa1.w;
    *(float4*)&Bs[0][br][bn] = pb0; *(float4*)&Bs[0][br+8][bn] = pb1;
    __syncthreads();

    const int nt = K >> 4;
    for (int it = 0; it < nt; it++) {
        const int buf = it & 1;
        if (it + 1 < nt) {
            const int k0 = (it + 1) << 4;
            pa0 = *(const float4*)&A[(size_t)(m0 + ar) * K + k0 + ak];
            pa1 = *(const float4*)&A[(size_t)(m0 + ar + 64) * K + k0 + ak];
            pb0 = *(const float4*)&B[(size_t)(k0 + br) * Nc + n0 + bn];
            pb1 = *(const float4*)&B[(size_t)(k0 + br + 8) * Nc + n0 + bn];
        }
        {
            const float (*as_)[132] = As[buf];
            const float (*bs_)[132] = Bs[buf];
#pragma unroll
            for (int kk = 0; kk < 16; kk++) KSTEP(as_, bs_, kk);
        }
        if (it + 1 < nt) {
            const int nb = buf ^ 1;
            As[nb][ak+0][ar]=pa0.x; As[nb][ak+1][ar]=pa0.y; As[nb][ak+2][ar]=pa0.z; As[nb][ak+3][ar]=pa0.w;
            As[nb][ak+0][ar+64]=pa1.x; As[nb][ak+1][ar+64]=pa1.y; As[nb][ak+2][ar+64]=pa1.z; As[nb][ak+3][ar+64]=pa1.w;
            *(float4*)&Bs[nb][br][bn] = pb0; *(float4*)&Bs[nb][br+8][bn] = pb1;
            __syncthreads();
        }
    }

#pragma unroll
    for (int i = 0; i < 8; i++) {
        const int m = m0 + ((i < 4) ? (ty4 + i) : (64 + ty4 + i - 4));
        const size_t rb = (size_t)m * Nc;
#pragma unroll
        for (int jh = 0; jh < 2; jh++) {
            const int n = n0 + jh * 64 + tx4;
            float4 r;
            r.x = cacc * acc[i][jh*4+0]; r.y = cacc * acc[i][jh*4+1];
            r.z = cacc * acc[i][jh*4+2]; r.w = cacc * acc[i][jh*4+3];
            if (bias) { float4 bb = *(const float4*)&bias[n];
                        r.x += bb.x; r.y += bb.y; r.z += bb.z; r.w += bb.w; }
            if (X1) { float4 q = *(const float4*)&X1[rb + n];
                      r.x = fmaf(c1,q.x,r.x); r.y = fmaf(c1,q.y,r.y);
                      r.z = fmaf(c1,q.z,r.z); r.w = fmaf(c1,q.w,r.w); }
            if (X2) { float4 q = *(const float4*)&X2[rb + n];
                      r.x = fmaf(c2,q.x,r.x); r.y = fmaf(c2,q.y,r.y);
                      r.z = fmaf(c2,q.z,r.z); r.w = fmaf(c2,q.w,r.w); }
            if (X3) { float4 q = *(const float4*)&X3[rb + n];
                      r.x = fmaf(c3,q.x,r.x); r.y = fmaf(c3,q.y,r.y);
                      r.z = fmaf(c3,q.z,r.z); r.w = fmaf(c3,q.w,r.w); }
            if (relu) { r.x = fmaxf(r.x,0.f); r.y = fmaxf(r.y,0.f);
                        r.z = fmaxf(r.z,0.f); r.w = fmaxf(r.w,0.f); }
            *(float4*)&C[rb + n] = r;
            if (C2) *(float4*)&C2[rb + n] = r;
        }
    }
}

// ---------------- scores: S = mask ? (QK^T/16 - |dy|) : NEG ----------------
__global__ __launch_bounds__(256) void scores128(
    const float* __restrict__ Q, const float* __restrict__ Km,
    const float* __restrict__ xyz,
    const void* __restrict__ dmask, const void* __restrict__ bmask,
    float* __restrict__ S)
{
    __shared__ __align__(16) float As[2][16][132];
    __shared__ __align__(16) float Bs[2][16][132];
    __shared__ float xi[128][3], xj[128][3], sqi[128], sqj[128], yi[128], yj[128];
    const int t = threadIdx.x;
    const int tx = t & 15, ty = t >> 4;
    const int tx4 = tx * 4, ty4 = ty * 4;
    const int i0 = blockIdx.y * 128, j0 = blockIdx.x * 128;
    const int ar = t >> 2, ak = (t & 3) * 4;

    if (t < 128) {
        float a = xyz[(i0+t)*3+0], b = xyz[(i0+t)*3+1], c = xyz[(i0+t)*3+2];
        xi[t][0]=a; xi[t][1]=b; xi[t][2]=c;
        sqi[t] = fmaf(c,c,fmaf(b,b,a*a));
        yi[t]  = g_y[i0+t];
    } else {
        int u = t - 128;
        float a = xyz[(j0+u)*3+0], b = xyz[(j0+u)*3+1], c = xyz[(j0+u)*3+2];
        xj[u][0]=a; xj[u][1]=b; xj[u][2]=c;
        sqj[u] = fmaf(c,c,fmaf(b,b,a*a));
        yj[u]  = g_y[j0+u];
    }

    float acc[8][8] = {};

    float4 pa0 = *(const float4*)&Q [(size_t)(i0 + ar) * HID_ + ak];
    float4 pa1 = *(const float4*)&Q [(size_t)(i0 + ar + 64) * HID_ + ak];
    float4 pb0 = *(const float4*)&Km[(size_t)(j0 + ar) * HID_ + ak];
    float4 pb1 = *(const float4*)&Km[(size_t)(j0 + ar + 64) * HID_ + ak];
    As[0][ak+0][ar]=pa0.x; As[0][ak+1][ar]=pa0.y; As[0][ak+2][ar]=pa0.z; As[0][ak+3][ar]=pa0.w;
    As[0][ak+0][ar+64]=pa1.x; As[0][ak+1][ar+64]=pa1.y; As[0][ak+2][ar+64]=pa1.z; As[0][ak+3][ar+64]=pa1.w;
    Bs[0][ak+0][ar]=pb0.x; Bs[0][ak+1][ar]=pb0.y; Bs[0][ak+2][ar]=pb0.z; Bs[0][ak+3][ar]=pb0.w;
    Bs[0][ak+0][ar+64]=pb1.x; Bs[0][ak+1][ar+64]=pb1.y; Bs[0][ak+2][ar+64]=pb1.z; Bs[0][ak+3][ar+64]=pb1.w;
    __syncthreads();

    const int nt = HID_ >> 4;
    for (int it = 0; it < nt; it++) {
        const int buf = it & 1;
        if (it + 1 < nt) {
            const int k0 = (it + 1) << 4;
            pa0 = *(const float4*)&Q [(size_t)(i0 + ar) * HID_ + k0 + ak];
            pa1 = *(const float4*)&Q [(size_t)(i0 + ar + 64) * HID_ + k0 + ak];
            pb0 = *(const float4*)&Km[(size_t)(j0 + ar) * HID_ + k0 + ak];
            pb1 = *(const float4*)&Km[(size_t)(j0 + ar + 64) * HID_ + k0 + ak];
        }
        {
            const float (*as_)[132] = As[buf];
            const float (*bs_)[132] = Bs[buf];
#pragma unroll
            for (int kk = 0; kk < 16; kk++) KSTEP(as_, bs_, kk);
        }
        if (it + 1 < nt) {
            const int nb = buf ^ 1;
            As[nb][ak+0][ar]=pa0.x; As[nb][ak+1][ar]=pa0.y; As[nb][ak+2][ar]=pa0.z; As[nb][ak+3][ar]=pa0.w;
            As[nb][ak+0][ar+64]=pa1.x; As[nb][ak+1][ar+64]=pa1.y; As[nb][ak+2][ar+64]=pa1.z; As[nb][ak+3][ar+64]=pa1.w;
            Bs[nb][ak+0][ar]=pb0.x; Bs[nb][ak+1][ar]=pb0.y; Bs[nb][ak+2][ar]=pb0.z; Bs[nb][ak+3][ar]=pb0.w;
            Bs[nb][ak+0][ar+64]=pb1.x; Bs[nb][ak+1][ar+64]=pb1.y; Bs[nb][ak+2][ar+64]=pb1.z; Bs[nb][ak+3][ar+64]=pb1.w;
            __syncthreads();
        }
    }

    const int mode = g_maskmode;
#pragma unroll
    for (int i = 0; i < 8; i++) {
        const int li = (i < 4) ? (ty4 + i) : (64 + ty4 + i - 4);
        const int gi = i0 + li;
        const float xa = xi[li][0], xb = xi[li][1], xc = xi[li][2];
        const float sqa = sqi[li], ya = yi[li];
        const size_t rb = (size_t)gi * N_;
#pragma unroll
        for (int j = 0; j < 8; j++) {
            const int lj = (j < 4) ? (tx4 + j) : (64 + tx4 + j - 4);
            const size_t idx = rb + j0 + lj;
            float dot = fmaf(xc, xj[lj][2], fmaf(xb, xj[lj][1], xa * xj[lj][0]));
            float dist2 = (sqa + sqj[lj]) - 2.0f * dot;
            bool ok = mask_at(dmask, idx, mode) && mask_at(bmask, idx, mode) && (dist2 <= 100.0f);
            S[idx] = ok ? (acc[i][j] * 0.0625f - fabsf(ya - yj[lj])) : NEG_;
        }
    }
}

// ---------------- softmax + attn@xyz fused ----------------
__global__ void softmax_xyz(float* __restrict__ S,
                            const float* __restrict__ xs, const float* __restrict__ ys,
                            const float* __restrict__ zs, float* __restrict__ out)
{
    __shared__ float r0[256], r1[256], r2[256];
    const int row = blockIdx.x, t = threadIdx.x;
    float* p = S + (size_t)row * N_;
    float4 v[4];
    float mx = -1e30f;
#pragma unroll
    for (int c = 0; c < 4; c++) {
        v[c] = *(float4*)&p[c*1024 + t*4];
        mx = fmaxf(mx, fmaxf(fmaxf(v[c].x, v[c].y), fmaxf(v[c].z, v[c].w)));
    }
    r0[t] = mx; __syncthreads();
    for (int s = 128; s > 0; s >>= 1) { if (t < s) r0[t] = fmaxf(r0[t], r0[t+s]); __syncthreads(); }
    mx = r0[0]; __syncthreads();
    float sum = 0.0f;
#pragma unroll
    for (int c = 0; c < 4; c++) {
        v[c].x = expf(v[c].x - mx); v[c].y = expf(v[c].y - mx);
        v[c].z = expf(v[c].z - mx); v[c].w = expf(v[c].w - mx);
        sum += v[c].x + v[c].y + v[c].z + v[c].w;
    }
    r0[t] = sum; __syncthreads();
    for (int s = 128; s > 0; s >>= 1) { if (t < s) r0[t] += r0[t+s]; __syncthreads(); }
    const float inv = 1.0f / r0[0];
    __syncthreads();
    float a0 = 0.f, a1 = 0.f, a2 = 0.f;
#pragma unroll
    for (int c = 0; c < 4; c++) {
        v[c].x *= inv; v[c].y *= inv; v[c].z *= inv; v[c].w *= inv;
        *(float4*)&p[c*1024 + t*4] = v[c];
        const int j = c*1024 + t*4;
        a0 = fmaf(v[c].x, xs[j], fmaf(v[c].y, xs[j+1], fmaf(v[c].z, xs[j+2], fmaf(v[c].w, xs[j+3], a0))));
        a1 = fmaf(v[c].x, ys[j], fmaf(v[c].y, ys[j+1], fmaf(v[c].z, ys[j+2], fmaf(v[c].w, ys[j+3], a1))));
        a2 = fmaf(v[c].x, zs[j], fmaf(v[c].y, zs[j+1], fmaf(v[c].z, zs[j+2], fmaf(v[c].w, zs[j+3], a2))));
    }
    r0[t]=a0; r1[t]=a1; r2[t]=a2; __syncthreads();
    for (int s = 128; s > 0; s >>= 1) {
        if (t < s) { r0[t]+=r0[t+s]; r1[t]+=r1[t+s]; r2[t]+=r2[t+s]; }
        __syncthreads();
    }
    if (t == 0) { out[row*3+0]=r0[0]; out[row*3+1]=r1[0]; out[row*3+2]=r2[0]; }
}

__global__ void xyz2soa(const float* __restrict__ xyz, float* __restrict__ xs,
                        float* __restrict__ ys, float* __restrict__ zs)
{
    int i = blockIdx.x * blockDim.x + threadIdx.x;
    if (i < N_) { xs[i] = xyz[3*i]; ys[i] = xyz[3*i+1]; zs[i] = xyz[3*i+2]; }
}

// ---------------- GAT pieces ----------------
__global__ void compute_elr(const float* __restrict__ hl, const float* __restrict__ al,
                            const float* __restrict__ ar)
{
    int idx = blockIdx.x * blockDim.x + threadIdx.x;
    if (idx >= N_*4) return;
    int node = idx >> 2, h = idx & 3;
    const float* row = hl + (size_t)node * HID_ + h * 64;
    float sl = 0.f, sr = 0.f;
#pragma unroll 8
    for (int d = 0; d < 64; d++) {
        float v = row[d];
        sl = fmaf(v, al[h*64+d], sl);
        sr = fmaf(v, ar[h*64+d], sr);
    }
    g_el[idx] = sl; g_er[idx] = sr;
}

__global__ void zero_cnt() { int i = blockIdx.x*blockDim.x + threadIdx.x; if (i < N_) g_cnt[i] = 0; }
__global__ void count_edges(const int* __restrict__ dst) {
    int e = blockIdx.x*blockDim.x + threadIdx.x; if (e < E_) atomicAdd(&g_cnt[dst[e]], 1);
}
__global__ void scan4096() {
    __shared__ int part[1024];
    int t = threadIdx.x, base = t * 4;
    int a0 = g_cnt[base], a1 = g_cnt[base+1], a2 = g_cnt[base+2], a3 = g_cnt[base+3];
    int s = a0 + a1 + a2 + a3;
    part[t] = s; __syncthreads();
    for (int off = 1; off < 1024; off <<= 1) {
        int v = (t >= off) ? part[t-off] : 0;
        __syncthreads();
        part[t] += v;
        __syncthreads();
    }
    int excl = part[t] - s;
    g_rowptr[base+0] = excl;           g_cur[base+0] = excl;
    g_rowptr[base+1] = excl+a0;        g_cur[base+1] = excl+a0;
    g_rowptr[base+2] = excl+a0+a1;     g_cur[base+2] = excl+a0+a1;
    g_rowptr[base+3] = excl+a0+a1+a2;  g_cur[base+3] = excl+a0+a1+a2;
    if (t == 1023) g_rowptr[4096] = part[1023];
}
__global__ void scatter_edges(const int* __restrict__ src, const int* __restrict__ dst) {
    int e = blockIdx.x*blockDim.x + threadIdx.x;
    if (e < E_) { int p = atomicAdd(&g_cur[dst[e]], 1); g_psrc[p] = src[e]; }
}

__global__ void gat_aggregate(const float* __restrict__ hl, float* __restrict__ xg)
{
    const int node = (blockIdx.x * blockDim.x + threadIdx.x) >> 5;
    const int lane = threadIdx.x & 31;
    if (node >= N_) return;
    const int beg = g_rowptr[node], end = g_rowptr[node+1];
    const float er_i = (lane < 4) ? g_er[node*4 + lane] : 0.f;
    float m = -1e30f;
    for (int p = beg; p < end; p++) {
        int s = g_psrc[p];
        if (lane < 4) {
            float v = g_el[s*4 + lane] + er_i;
            float e = (v > 0.f) ? v : 0.2f * v;
            m = fmaxf(m, e);
        }
    }
    float m0 = __shfl_sync(0xffffffffu, m, 0), m1 = __shfl_sync(0xffffffffu, m, 1);
    float m2 = __shfl_sync(0xffffffffu, m, 2), m3 = __shfl_sync(0xffffffffu, m, 3);
    const int myh = lane >> 3;
    float4 acc0 = {0,0,0,0}, acc1 = {0,0,0,0};
    float z = 0.f;
    for (int p = beg; p < end; p++) {
        int s = g_psrc[p];
        float w = 0.f;
        if (lane < 4) {
            float v = g_el[s*4 + lane] + er_i;
            float e = (v > 0.f) ? v : 0.2f * v;
            float mm = (lane==0)?m0:(lane==1)?m1:(lane==2)?m2:m3;
            w = expf(e - mm);
            z += w;
        }
        float w0 = __shfl_sync(0xffffffffu, w, 0), w1 = __shfl_sync(0xffffffffu, w, 1);
        float w2 = __shfl_sync(0xffffffffu, w, 2), w3 = __shfl_sync(0xffffffffu, w, 3);
        float wm = (myh==0)?w0:(myh==1)?w1:(myh==2)?w2:w3;
        const float4* hp = (const float4*)(hl + (size_t)s * HID_ + lane * 8);
        float4 hv0 = hp[0], hv1 = hp[1];
        acc0.x=fmaf(wm,hv0.x,acc0.x); acc0.y=fmaf(wm,hv0.y,acc0.y);
        acc0.z=fmaf(wm,hv0.z,acc0.z); acc0.w=fmaf(wm,hv0.w,acc0.w);
        acc1.x=fmaf(wm,hv1.x,acc1.x); acc1.y=fmaf(wm,hv1.y,acc1.y);
        acc1.z=fmaf(wm,hv1.z,acc1.z); acc1.w=fmaf(wm,hv1.w,acc1.w);
    }
    float z0 = __shfl_sync(0xffffffffu, z, 0), z1 = __shfl_sync(0xffffffffu, z, 1);
    float z2 = __shfl_sync(0xffffffffu, z, 2), z3 = __shfl_sync(0xffffffffu, z, 3);
    float zm = (myh==0)?z0:(myh==1)?z1:(myh==2)?z2:z3;
    float inv = 1.0f / (zm + 1e-9f);
    acc0.x*=inv; acc0.y*=inv; acc0.z*=inv; acc0.w*=inv;
    acc1.x*=inv; acc1.y*=inv; acc1.z*=inv; acc1.w*=inv;
    float4* op = (float4*)(xg + (size_t)node * HID_ + lane * 8);
    op[0] = acc0; op[1] = acc1;
}

__global__ void pack_support(const float* __restrict__ xg, const float* __restrict__ h0,
                             float* __restrict__ sup)
{
    int i = blockIdx.x * blockDim.x + threadIdx.x;
    if (i >= N_ * 512) return;
    int r = i >> 9, c = i & 511;
    sup[i] = (c < 256) ? xg[(size_t)r*256 + c] : h0[(size_t)r*256 + (c-256)];
}

__global__ void yhat_k(const float* __restrict__ x, const float* __restrict__ W,
                       const float* __restrict__ b)
{
    int i = blockIdx.x * blockDim.x + threadIdx.x;
    if (i >= N_) return;
    const float* r = x + (size_t)i * HID_;
    float l0 = b[0], l1 = b[1];
#pragma unroll 8
    for (int d = 0; d < HID_; d++) {
        float v = r[d];
        l0 = fmaf(v, W[2*d+0], l0);
        l1 = fmaf(v, W[2*d+1], l1);
    }
    g_y[i] = 1.0f / (1.0f + expf(l0 - l1));
}

__global__ void cls_k(const float* __restrict__ x, const float* __restrict__ W,
                      const float* __restrict__ b, float* __restrict__ out)
{
    int i = blockIdx.x * blockDim.x + threadIdx.x;
    if (i >= N_) return;
    const float* r = x + (size_t)i * HID_;
    float l0 = b[0], l1 = b[1];
#pragma unroll 8
    for (int d = 0; d < HID_; d++) {
        float v = r[d];
        l0 = fmaf(v, W[2*d+0], l0);
        l1 = fmaf(v, W[2*d+1], l1);
    }
    out[2*i+0] = l0;
    out[2*i+1] = l1;
}

// ---------------- host orchestration ----------------
extern "C" void kernel_launch(void* const* d_in, const int* in_sizes, int n_in,
                              void* d_out, int out_size)
{
    const float* feat   = (const float*)d_in[0];
    const float* xyz_in = (const float*)d_in[1];
    const int*   src    = (const int*)  d_in[2];
    const int*   dst    = (const int*)  d_in[3];
    const void*  dmask  = d_in[4];
    const void*  bmask  = d_in[5];
    const float* fcW  = (const float*)d_in[6];
    const float* fcb  = (const float*)d_in[7];
    const float* gatW = (const float*)d_in[8];
    const float* al   = (const float*)d_in[9];
    const float* ar   = (const float*)d_in[10];
    const float* gcW  = (const float*)d_in[11];
    const float* cgW  = (const float*)d_in[12];
    const float* cgb  = (const float*)d_in[13];
    const float* qW   = (const float*)d_in[14];
    const float* qb   = (const float*)d_in[15];
    const float* kW   = (const float*)d_in[16];
    const float* kb   = (const float*)d_in[17];
    const float* vW   = (const float*)d_in[18];
    const float* vb   = (const float*)d_in[19];
    const float* oW   = (const float*)d_in[20];
    const float* ob   = (const float*)d_in[21];
    const float* clsW = (const float*)d_in[22];
    const float* clsb = (const float*)d_in[23];

    float *px, *ph0, *phl, *pxg, *psup, *pq, *pk, *pv, *phms, *pS, *pxyz0, *pxyz1;
    float *pxs, *pys, *pzs;
    cudaGetSymbolAddress((void**)&px,    g_x);
    cudaGetSymbolAddress((void**)&ph0,   g_h0);
    cudaGetSymbolAddress((void**)&phl,   g_hl);
    cudaGetSymbolAddress((void**)&pxg,   g_xg);
    cudaGetSymbolAddress((void**)&psup,  g_sup);
    cudaGetSymbolAddress((void**)&pq,    g_q);
    cudaGetSymbolAddress((void**)&pk,    g_k);
    cudaGetSymbolAddress((void**)&pv,    g_v);
    cudaGetSymbolAddress((void**)&phms,  g_hms);
    cudaGetSymbolAddress((void**)&pS,    g_S);
    cudaGetSymbolAddress((void**)&pxyz0, g_xyz0);
    cudaGetSymbolAddress((void**)&pxyz1, g_xyz1);
    cudaGetSymbolAddress((void**)&pxs,   g_xs);
    cudaGetSymbolAddress((void**)&pys,   g_ys);
    cudaGetSymbolAddress((void**)&pzs,   g_zs);

    detect_mask_mode<<<1, 1>>>((const unsigned int*)dmask);

    sgemm128<<<dim3(HID_/128, N_/128), 256>>>(feat, fcW, px, ph0, N_, HID_, FEAT_,
                                              fcb, 1, 1.0f, nullptr,0.f, nullptr,0.f, nullptr,0.f);

    zero_cnt<<<N_/256, 256>>>();
    count_edges<<<E_/256, 256>>>(dst);
    scan4096<<<1, 1024>>>();
    scatter_edges<<<E_/256, 256>>>(src, dst);

    const float ALPHA = 0.1f, LAMDA = 0.5f;
    for (int l = 0; l < 4; l++) {
        sgemm128<<<dim3(HID_/128, N_/128), 256>>>(px, gatW + (size_t)l*HID_*HID_, phl, nullptr,
                                                  N_, HID_, HID_, nullptr, 0, 1.0f,
                                                  nullptr,0.f, nullptr,0.f, nullptr,0.f);
        compute_elr<<<(N_*4)/256, 256>>>(phl, al + l*4*64, ar + l*4*64);
        gat_aggregate<<<N_/8, 256>>>(phl, pxg);
        pack_support<<<(N_*512)/256, 256>>>(pxg, ph0, psup);
        float theta = fminf(1.0f, logf(LAMDA / (float)(l + 1) + 1.0f));
        sgemm128<<<dim3(HID_/128, N_/128), 256>>>(psup, gcW + (size_t)l*512*HID_, px, nullptr,
                                                  N_, HID_, 512, nullptr, 0, theta,
                                                  pxg, (1.0f-theta)*(1.0f-ALPHA),
                                                  ph0, (1.0f-theta)*ALPHA,
                                                  px,  1.0f);
    }

    yhat_k<<<N_/256, 256>>>(px, cgW, cgb);

    const float* xyz_cur = xyz_in;
    float* xyz_buf[2] = { pxyz0, pxyz1 };
    for (int l = 0; l < 4; l++) {
        sgemm128<<<dim3(HID_/128, N_/128), 256>>>(px, qW + (size_t)l*HID_*HID_, pq, nullptr,
                                                  N_, HID_, HID_, qb + l*HID_, 0, 1.0f,
                                                  nullptr,0.f, nullptr,0.f, nullptr,0.f);
        sgemm128<<<dim3(HID_/128, N_/128), 256>>>(px, kW + (size_t)l*HID_*HID_, pk, nullptr,
                                                  N_, HID_, HID_, kb + l*HID_, 0, 1.0f,
                                                  nullptr,0.f, nullptr,0.f, nullptr,0.f);
        sgemm128<<<dim3(HID_/128, N_/128), 256>>>(px, vW + (size_t)l*HID_*HID_, pv, nullptr,
                                                  N_, HID_, HID_, vb + l*HID_, 0, 1.0f,
                                                  nullptr,0.f, nullptr,0.f, nullptr,0.f);
        scores128<<<dim3(N_/128, N_/128), 256>>>(pq, pk, xyz_cur, dmask, bmask, pS);
        xyz2soa<<<N_/256, 256>>>(xyz_cur, pxs, pys, pzs);
        softmax_xyz<<<N_, 256>>>(pS, pxs, pys, pzs, xyz_buf[l & 1]);
        sgemm128<<<dim3(HID_/128, N_/128), 256>>>(pS, pv, phms, nullptr, N_, HID_, N_,
                                                  nullptr, 0, 1.0f,
                                                  nullptr,0.f, nullptr,0.f, nullptr,0.f);
        sgemm128<<<dim3(HID_/128, N_/128), 256>>>(phms, oW + (size_t)l*HID_*HID_, px, nullptr,
                                                  N_, HID_, HID_, ob + l*HID_, 0, 1.0f,
                                                  px, 1.0f, nullptr,0.f, nullptr,0.f);
        xyz_cur = xyz_buf[l & 1];
    }

    cls_k<<<N_/256, 256>>>(px, clsW, clsb, (float*)d_out);
}

// round 5
// speedup vs baseline: 1.5861x; 1.2943x over previous
#include <cuda_runtime.h>
#include <math.h>

#define N_    4096
#define E_    131072
#define FEAT_ 64
#define HID_  256
#define NEG_  (-1e9f)
#define KCHUNKS_ 4
#define KCHUNK_  (N_ / KCHUNKS_)

// ---------------- scratch ----------------
__device__ float g_h0 [N_*HID_];
__device__ float g_x  [N_*HID_];
__device__ float g_hl [N_*HID_];
__device__ float g_xg [N_*HID_];
__device__ float g_sup[N_*2*HID_];
__device__ float g_q  [N_*HID_];
__device__ float g_k  [N_*HID_];
__device__ float g_v  [N_*HID_];
__device__ float g_hms[N_*HID_];
__device__ float g_part[(size_t)KCHUNKS_*N_*HID_];
__device__ float g_S  [(size_t)N_*N_];
__device__ float g_el [N_*4];
__device__ float g_er [N_*4];
__device__ float g_y  [N_];
__device__ float g_xyz0[N_*3];
__device__ float g_xyz1[N_*3];
__device__ float g_xs[N_], g_ys[N_], g_zs[N_];
__device__ int   g_cnt[N_];
__device__ int   g_rowptr[N_+1];
__device__ int   g_cur[N_];
__device__ int   g_psrc[E_];
__device__ int   g_maskmode;

// ---------------- mask handling ----------------
__global__ void detect_mask_mode(const unsigned int* __restrict__ m) {
    bool allbin = true, anyfloat = false;
    for (int i = 0; i < 1024; i++) {
        unsigned int w = m[i];
        if (w == 0x3f800000u) anyfloat = true;
        if (w > 1u) allbin = false;
    }
    g_maskmode = anyfloat ? 2 : (allbin ? 1 : 0);
}
__device__ __forceinline__ bool mask_at(const void* p, size_t i, int mode) {
    if (mode == 0) return ((const unsigned char*)p)[i] != 0;
    if (mode == 1) return ((const int*)p)[i] != 0;
    return ((const float*)p)[i] != 0.0f;
}

// ================= 64x64x16 SGEMM (small-N GEMMs; full epilogue) =================
__global__ void sgemm64(const float* __restrict__ A, const float* __restrict__ B,
                        float* __restrict__ C, float* __restrict__ C2,
                        int M, int Nc, int K,
                        const float* __restrict__ bias, int relu, float cacc,
                        const float* __restrict__ X1, float c1,
                        const float* __restrict__ X2, float c2,
                        const float* __restrict__ X3, float c3)
{
    __shared__ __align__(16) float As[16][68];
    __shared__ __align__(16) float Bs[16][68];
    const int t  = threadIdx.x;
    const int tx = t & 15, ty = t >> 4;
    const int m0 = blockIdx.y * 64, n0 = blockIdx.x * 64;
    const int ra = t >> 2, kq = t & 3;
    const int kr = t >> 4, nq = t & 15;

    float acc[4][4] = {};
    for (int k0 = 0; k0 < K; k0 += 16) {
        float4 a = *(const float4*)&A[(size_t)(m0 + ra) * K + k0 + kq * 4];
        As[kq*4+0][ra] = a.x; As[kq*4+1][ra] = a.y; As[kq*4+2][ra] = a.z; As[kq*4+3][ra] = a.w;
        float4 b = *(const float4*)&B[(size_t)(k0 + kr) * Nc + n0 + nq * 4];
        *(float4*)&Bs[kr][nq*4] = b;
        __syncthreads();
#pragma unroll
        for (int kk = 0; kk < 16; kk++) {
            float4 av = *(float4*)&As[kk][ty*4];
            float4 bv = *(float4*)&Bs[kk][tx*4];
            acc[0][0]=fmaf(av.x,bv.x,acc[0][0]); acc[0][1]=fmaf(av.x,bv.y,acc[0][1]);
            acc[0][2]=fmaf(av.x,bv.z,acc[0][2]); acc[0][3]=fmaf(av.x,bv.w,acc[0][3]);
            acc[1][0]=fmaf(av.y,bv.x,acc[1][0]); acc[1][1]=fmaf(av.y,bv.y,acc[1][1]);
            acc[1][2]=fmaf(av.y,bv.z,acc[1][2]); acc[1][3]=fmaf(av.y,bv.w,acc[1][3]);
            acc[2][0]=fmaf(av.z,bv.x,acc[2][0]); acc[2][1]=fmaf(av.z,bv.y,acc[2][1]);
            acc[2][2]=fmaf(av.z,bv.z,acc[2][2]); acc[2][3]=fmaf(av.z,bv.w,acc[2][3]);
            acc[3][0]=fmaf(av.w,bv.x,acc[3][0]); acc[3][1]=fmaf(av.w,bv.y,acc[3][1]);
            acc[3][2]=fmaf(av.w,bv.z,acc[3][2]); acc[3][3]=fmaf(av.w,bv.w,acc[3][3]);
        }
        __syncthreads();
    }
#pragma unroll
    for (int i = 0; i < 4; i++) {
        int m = m0 + ty*4 + i;
#pragma unroll
        for (int j = 0; j < 4; j++) {
            int n = n0 + tx*4 + j;
            size_t idx = (size_t)m * Nc + n;
            float v = cacc * acc[i][j];
            if (bias) v += bias[n];
            if (X1) v += c1 * X1[idx];
            if (X2) v += c2 * X2[idx];
            if (X3) v += c3 * X3[idx];
            if (relu) v = fmaxf(v, 0.0f);
            C[idx] = v;
            if (C2) C2[idx] = v;
        }
    }
}

// ================= 128x128 8x8-microtile core (shared by scores & split-K) =================
#define KSTEP(ASB, BSB, kk)                                                     \
    do {                                                                        \
        float4 a0_ = *(const float4*)&ASB[kk][ty4];                             \
        float4 a1_ = *(const float4*)&ASB[kk][ty4 + 64];                        \
        float4 b0_ = *(const float4*)&BSB[kk][tx4];                             \
        float4 b1_ = *(const float4*)&BSB[kk][tx4 + 64];                        \
        const float ax_[8] = {a0_.x,a0_.y,a0_.z,a0_.w,a1_.x,a1_.y,a1_.z,a1_.w}; \
        const float bx_[8] = {b0_.x,b0_.y,b0_.z,b0_.w,b1_.x,b1_.y,b1_.z,b1_.w}; \
        _Pragma("unroll")                                                       \
        for (int i_ = 0; i_ < 8; i_++)                                          \
            _Pragma("unroll")                                                   \
            for (int j_ = 0; j_ < 8; j_++)                                      \
                acc[i_][j_] = fmaf(ax_[i_], bx_[j_], acc[i_][j_]);              \
    } while (0)

// split-K GEMM: Cpart[z] = A[:, zK..zK+chunk) @ B[zK..zK+chunk, :]
__global__ __launch_bounds__(256) void sgemm128_splitk(
    const float* __restrict__ A, const float* __restrict__ B,
    float* __restrict__ Cpart, int M, int Nc, int Ktotal)
{
    __shared__ __align__(16) float As[2][16][132];
    __shared__ __align__(16) float Bs[2][16][132];
    const int t = threadIdx.x;
    const int tx = t & 15, ty = t >> 4;
    const int tx4 = tx * 4, ty4 = ty * 4;
    const int m0 = blockIdx.y * 128, n0 = blockIdx.x * 128;
    const int kbase = blockIdx.z * KCHUNK_;
    const int ar = t >> 2, ak = (t & 3) * 4;
    const int br = t >> 5, bn = (t & 31) * 4;

    float acc[8][8] = {};

    float4 pa0 = *(const float4*)&A[(size_t)(m0 + ar) * Ktotal + kbase + ak];
    float4 pa1 = *(const float4*)&A[(size_t)(m0 + ar + 64) * Ktotal + kbase + ak];
    float4 pb0 = *(const float4*)&B[(size_t)(kbase + br) * Nc + n0 + bn];
    float4 pb1 = *(const float4*)&B[(size_t)(kbase + br + 8) * Nc + n0 + bn];
    As[0][ak+0][ar]=pa0.x; As[0][ak+1][ar]=pa0.y; As[0][ak+2][ar]=pa0.z; As[0][ak+3][ar]=pa0.w;
    As[0][ak+0][ar+64]=pa1.x; As[0][ak+1][ar+64]=pa1.y; As[0][ak+2][ar+64]=pa1.z; As[0][ak+3][ar+64]=pa1.w;
    *(float4*)&Bs[0][br][bn] = pb0; *(float4*)&Bs[0][br+8][bn] = pb1;
    __syncthreads();

    const int nt = KCHUNK_ >> 4;
    for (int it = 0; it < nt; it++) {
        const int buf = it & 1;
        if (it + 1 < nt) {
            const int k0 = kbase + ((it + 1) << 4);
            pa0 = *(const float4*)&A[(size_t)(m0 + ar) * Ktotal + k0 + ak];
            pa1 = *(const float4*)&A[(size_t)(m0 + ar + 64) * Ktotal + k0 + ak];
            pb0 = *(const float4*)&B[(size_t)(k0 + br) * Nc + n0 + bn];
            pb1 = *(const float4*)&B[(size_t)(k0 + br + 8) * Nc + n0 + bn];
        }
        {
            const float (*as_)[132] = As[buf];
            const float (*bs_)[132] = Bs[buf];
#pragma unroll
            for (int kk = 0; kk < 16; kk++) KSTEP(as_, bs_, kk);
        }
        if (it + 1 < nt) {
            const int nb = buf ^ 1;
            As[nb][ak+0][ar]=pa0.x; As[nb][ak+1][ar]=pa0.y; As[nb][ak+2][ar]=pa0.z; As[nb][ak+3][ar]=pa0.w;
            As[nb][ak+0][ar+64]=pa1.x; As[nb][ak+1][ar+64]=pa1.y; As[nb][ak+2][ar+64]=pa1.z; As[nb][ak+3][ar+64]=pa1.w;
            *(float4*)&Bs[nb][br][bn] = pb0; *(float4*)&Bs[nb][br+8][bn] = pb1;
            __syncthreads();
        }
    }

    float* Cz = Cpart + (size_t)blockIdx.z * M * Nc;
#pragma unroll
    for (int i = 0; i < 8; i++) {
        const int m = m0 + ((i < 4) ? (ty4 + i) : (64 + ty4 + i - 4));
        const size_t rb = (size_t)m * Nc;
#pragma unroll
        for (int jh = 0; jh < 2; jh++) {
            const int n = n0 + jh * 64 + tx4;
            float4 r = { acc[i][jh*4+0], acc[i][jh*4+1], acc[i][jh*4+2], acc[i][jh*4+3] };
            *(float4*)&Cz[rb + n] = r;
        }
    }
}

__global__ void combine_parts(const float* __restrict__ P, float* __restrict__ C)
{
    int i = blockIdx.x * blockDim.x + threadIdx.x;
    const size_t n = (size_t)N_ * HID_;
    float4 a = *(const float4*)&P[(size_t)i*4];
    float4 b = *(const float4*)&P[n + (size_t)i*4];
    float4 c = *(const float4*)&P[2*n + (size_t)i*4];
    float4 d = *(const float4*)&P[3*n + (size_t)i*4];
    float4 r = { a.x+b.x+c.x+d.x, a.y+b.y+c.y+d.y, a.z+b.z+c.z+d.z, a.w+b.w+c.w+d.w };
    *(float4*)&C[(size_t)i*4] = r;
}

// ---------------- scores: S = mask ? (QK^T/16 - |dy|) : NEG ----------------
__global__ __launch_bounds__(256) void scores128(
    const float* __restrict__ Q, const float* __restrict__ Km,
    const float* __restrict__ xyz,
    const void* __restrict__ dmask, const void* __restrict__ bmask,
    float* __restrict__ S)
{
    __shared__ __align__(16) float As[2][16][132];
    __shared__ __align__(16) float Bs[2][16][132];
    __shared__ float xi[128][3], xj[128][3], sqi[128], sqj[128], yi[128], yj[128];
    const int t = threadIdx.x;
    const int tx = t & 15, ty = t >> 4;
    const int tx4 = tx * 4, ty4 = ty * 4;
    const int i0 = blockIdx.y * 128, j0 = blockIdx.x * 128;
    const int ar = t >> 2, ak = (t & 3) * 4;

    if (t < 128) {
        float a = xyz[(i0+t)*3+0], b = xyz[(i0+t)*3+1], c = xyz[(i0+t)*3+2];
        xi[t][0]=a; xi[t][1]=b; xi[t][2]=c;
        sqi[t] = fmaf(c,c,fmaf(b,b,a*a));
        yi[t]  = g_y[i0+t];
    } else {
        int u = t - 128;
        float a = xyz[(j0+u)*3+0], b = xyz[(j0+u)*3+1], c = xyz[(j0+u)*3+2];
        xj[u][0]=a; xj[u][1]=b; xj[u][2]=c;
        sqj[u] = fmaf(c,c,fmaf(b,b,a*a));
        yj[u]  = g_y[j0+u];
    }

    float acc[8][8] = {};

    float4 pa0 = *(const float4*)&Q [(size_t)(i0 + ar) * HID_ + ak];
    float4 pa1 = *(const float4*)&Q [(size_t)(i0 + ar + 64) * HID_ + ak];
    float4 pb0 = *(const float4*)&Km[(size_t)(j0 + ar) * HID_ + ak];
    float4 pb1 = *(const float4*)&Km[(size_t)(j0 + ar + 64) * HID_ + ak];
    As[0][ak+0][ar]=pa0.x; As[0][ak+1][ar]=pa0.y; As[0][ak+2][ar]=pa0.z; As[0][ak+3][ar]=pa0.w;
    As[0][ak+0][ar+64]=pa1.x; As[0][ak+1][ar+64]=pa1.y; As[0][ak+2][ar+64]=pa1.z; As[0][ak+3][ar+64]=pa1.w;
    Bs[0][ak+0][ar]=pb0.x; Bs[0][ak+1][ar]=pb0.y; Bs[0][ak+2][ar]=pb0.z; Bs[0][ak+3][ar]=pb0.w;
    Bs[0][ak+0][ar+64]=pb1.x; Bs[0][ak+1][ar+64]=pb1.y; Bs[0][ak+2][ar+64]=pb1.z; Bs[0][ak+3][ar+64]=pb1.w;
    __syncthreads();

    const int nt = HID_ >> 4;
    for (int it = 0; it < nt; it++) {
        const int buf = it & 1;
        if (it + 1 < nt) {
            const int k0 = (it + 1) << 4;
            pa0 = *(const float4*)&Q [(size_t)(i0 + ar) * HID_ + k0 + ak];
            pa1 = *(const float4*)&Q [(size_t)(i0 + ar + 64) * HID_ + k0 + ak];
            pb0 = *(const float4*)&Km[(size_t)(j0 + ar) * HID_ + k0 + ak];
            pb1 = *(const float4*)&Km[(size_t)(j0 + ar + 64) * HID_ + k0 + ak];
        }
        {
            const float (*as_)[132] = As[buf];
            const float (*bs_)[132] = Bs[buf];
#pragma unroll
            for (int kk = 0; kk < 16; kk++) KSTEP(as_, bs_, kk);
        }
        if (it + 1 < nt) {
            const int nb = buf ^ 1;
            As[nb][ak+0][ar]=pa0.x; As[nb][ak+1][ar]=pa0.y; As[nb][ak+2][ar]=pa0.z; As[nb][ak+3][ar]=pa0.w;
            As[nb][ak+0][ar+64]=pa1.x; As[nb][ak+1][ar+64]=pa1.y; As[nb][ak+2][ar+64]=pa1.z; As[nb][ak+3][ar+64]=pa1.w;
            Bs[nb][ak+0][ar]=pb0.x; Bs[nb][ak+1][ar]=pb0.y; Bs[nb][ak+2][ar]=pb0.z; Bs[nb][ak+3][ar]=pb0.w;
            Bs[nb][ak+0][ar+64]=pb1.x; Bs[nb][ak+1][ar+64]=pb1.y; Bs[nb][ak+2][ar+64]=pb1.z; Bs[nb][ak+3][ar+64]=pb1.w;
            __syncthreads();
        }
    }

    const int mode = g_maskmode;
#pragma unroll
    for (int i = 0; i < 8; i++) {
        const int li = (i < 4) ? (ty4 + i) : (64 + ty4 + i - 4);
        const int gi = i0 + li;
        const float xa = xi[li][0], xb = xi[li][1], xc = xi[li][2];
        const float sqa = sqi[li], ya = yi[li];
        const size_t rb = (size_t)gi * N_;
#pragma unroll
        for (int j = 0; j < 8; j++) {
            const int lj = (j < 4) ? (tx4 + j) : (64 + tx4 + j - 4);
            const size_t idx = rb + j0 + lj;
            float dot = fmaf(xc, xj[lj][2], fmaf(xb, xj[lj][1], xa * xj[lj][0]));
            float dist2 = (sqa + sqj[lj]) - 2.0f * dot;
            bool ok = mask_at(dmask, idx, mode) && mask_at(bmask, idx, mode) && (dist2 <= 100.0f);
            S[idx] = ok ? (acc[i][j] * 0.0625f - fabsf(ya - yj[lj])) : NEG_;
        }
    }
}

// ---------------- softmax + attn@xyz fused ----------------
__global__ void softmax_xyz(float* __restrict__ S,
                            const float* __restrict__ xs, const float* __restrict__ ys,
                            const float* __restrict__ zs, float* __restrict__ out)
{
    __shared__ float r0[256], r1[256], r2[256];
    const int row = blockIdx.x, t = threadIdx.x;
    float* p = S + (size_t)row * N_;
    float4 v[4];
    float mx = -1e30f;
#pragma unroll
    for (int c = 0; c < 4; c++) {
        v[c] = *(float4*)&p[c*1024 + t*4];
        mx = fmaxf(mx, fmaxf(fmaxf(v[c].x, v[c].y), fmaxf(v[c].z, v[c].w)));
    }
    r0[t] = mx; __syncthreads();
    for (int s = 128; s > 0; s >>= 1) { if (t < s) r0[t] = fmaxf(r0[t], r0[t+s]); __syncthreads(); }
    mx = r0[0]; __syncthreads();
    float sum = 0.0f;
#pragma unroll
    for (int c = 0; c < 4; c++) {
        v[c].x = expf(v[c].x - mx); v[c].y = expf(v[c].y - mx);
        v[c].z = expf(v[c].z - mx); v[c].w = expf(v[c].w - mx);
        sum += v[c].x + v[c].y + v[c].z + v[c].w;
    }
    r0[t] = sum; __syncthreads();
    for (int s = 128; s > 0; s >>= 1) { if (t < s) r0[t] += r0[t+s]; __syncthreads(); }
    const float inv = 1.0f / r0[0];
    __syncthreads();
    float a0 = 0.f, a1 = 0.f, a2 = 0.f;
#pragma unroll
    for (int c = 0; c < 4; c++) {
        v[c].x *= inv; v[c].y *= inv; v[c].z *= inv; v[c].w *= inv;
        *(float4*)&p[c*1024 + t*4] = v[c];
        const int j = c*1024 + t*4;
        a0 = fmaf(v[c].x, xs[j], fmaf(v[c].y, xs[j+1], fmaf(v[c].z, xs[j+2], fmaf(v[c].w, xs[j+3], a0))));
        a1 = fmaf(v[c].x, ys[j], fmaf(v[c].y, ys[j+1], fmaf(v[c].z, ys[j+2], fmaf(v[c].w, ys[j+3], a1))));
        a2 = fmaf(v[c].x, zs[j], fmaf(v[c].y, zs[j+1], fmaf(v[c].z, zs[j+2], fmaf(v[c].w, zs[j+3], a2))));
    }
    r0[t]=a0; r1[t]=a1; r2[t]=a2; __syncthreads();
    for (int s = 128; s > 0; s >>= 1) {
        if (t < s) { r0[t]+=r0[t+s]; r1[t]+=r1[t+s]; r2[t]+=r2[t+s]; }
        __syncthreads();
    }
    if (t == 0) { out[row*3+0]=r0[0]; out[row*3+1]=r1[0]; out[row*3+2]=r2[0]; }
}

__global__ void xyz2soa(const float* __restrict__ xyz, float* __restrict__ xs,
                        float* __restrict__ ys, float* __restrict__ zs)
{
    int i = blockIdx.x * blockDim.x + threadIdx.x;
    if (i < N_) { xs[i] = xyz[3*i]; ys[i] = xyz[3*i+1]; zs[i] = xyz[3*i+2]; }
}

// ---------------- GAT pieces ----------------
__global__ void compute_elr(const float* __restrict__ hl, const float* __restrict__ al,
                            const float* __restrict__ ar)
{
    int idx = blockIdx.x * blockDim.x + threadIdx.x;
    if (idx >= N_*4) return;
    int node = idx >> 2, h = idx & 3;
    const float* row = hl + (size_t)node * HID_ + h * 64;
    float sl = 0.f, sr = 0.f;
#pragma unroll 8
    for (int d = 0; d < 64; d++) {
        float v = row[d];
        sl = fmaf(v, al[h*64+d], sl);
        sr = fmaf(v, ar[h*64+d], sr);
    }
    g_el[idx] = sl; g_er[idx] = sr;
}

__global__ void zero_cnt() { int i = blockIdx.x*blockDim.x + threadIdx.x; if (i < N_) g_cnt[i] = 0; }
__global__ void count_edges(const int* __restrict__ dst) {
    int e = blockIdx.x*blockDim.x + threadIdx.x; if (e < E_) atomicAdd(&g_cnt[dst[e]], 1);
}
__global__ void scan4096() {
    __shared__ int part[1024];
    int t = threadIdx.x, base = t * 4;
    int a0 = g_cnt[base], a1 = g_cnt[base+1], a2 = g_cnt[base+2], a3 = g_cnt[base+3];
    int s = a0 + a1 + a2 + a3;
    part[t] = s; __syncthreads();
    for (int off = 1; off < 1024; off <<= 1) {
        int v = (t >= off) ? part[t-off] : 0;
        __syncthreads();
        part[t] += v;
        __syncthreads();
    }
    int excl = part[t] - s;
    g_rowptr[base+0] = excl;           g_cur[base+0] = excl;
    g_rowptr[base+1] = excl+a0;        g_cur[base+1] = excl+a0;
    g_rowptr[base+2] = excl+a0+a1;     g_cur[base+2] = excl+a0+a1;
    g_rowptr[base+3] = excl+a0+a1+a2;  g_cur[base+3] = excl+a0+a1+a2;
    if (t == 1023) g_rowptr[4096] = part[1023];
}
__global__ void scatter_edges(const int* __restrict__ src, const int* __restrict__ dst) {
    int e = blockIdx.x*blockDim.x + threadIdx.x;
    if (e < E_) { int p = atomicAdd(&g_cur[dst[e]], 1); g_psrc[p] = src[e]; }
}

__global__ void gat_aggregate(const float* __restrict__ hl, float* __restrict__ xg)
{
    const int node = (blockIdx.x * blockDim.x + threadIdx.x) >> 5;
    const int lane = threadIdx.x & 31;
    if (node >= N_) return;
    const int beg = g_rowptr[node], end = g_rowptr[node+1];
    const float er_i = (lane < 4) ? g_er[node*4 + lane] : 0.f;
    float m = -1e30f;
    for (int p = beg; p < end; p++) {
        int s = g_psrc[p];
        if (lane < 4) {
            float v = g_el[s*4 + lane] + er_i;
            float e = (v > 0.f) ? v : 0.2f * v;
            m = fmaxf(m, e);
        }
    }
    float m0 = __shfl_sync(0xffffffffu, m, 0), m1 = __shfl_sync(0xffffffffu, m, 1);
    float m2 = __shfl_sync(0xffffffffu, m, 2), m3 = __shfl_sync(0xffffffffu, m, 3);
    const int myh = lane >> 3;
    float4 acc0 = {0,0,0,0}, acc1 = {0,0,0,0};
    float z = 0.f;
    for (int p = beg; p < end; p++) {
        int s = g_psrc[p];
        float w = 0.f;
        if (lane < 4) {
            float v = g_el[s*4 + lane] + er_i;
            float e = (v > 0.f) ? v : 0.2f * v;
            float mm = (lane==0)?m0:(lane==1)?m1:(lane==2)?m2:m3;
            w = expf(e - mm);
            z += w;
        }
        float w0 = __shfl_sync(0xffffffffu, w, 0), w1 = __shfl_sync(0xffffffffu, w, 1);
        float w2 = __shfl_sync(0xffffffffu, w, 2), w3 = __shfl_sync(0xffffffffu, w, 3);
        float wm = (myh==0)?w0:(myh==1)?w1:(myh==2)?w2:w3;
        const float4* hp = (const float4*)(hl + (size_t)s * HID_ + lane * 8);
        float4 hv0 = hp[0], hv1 = hp[1];
        acc0.x=fmaf(wm,hv0.x,acc0.x); acc0.y=fmaf(wm,hv0.y,acc0.y);
        acc0.z=fmaf(wm,hv0.z,acc0.z); acc0.w=fmaf(wm,hv0.w,acc0.w);
        acc1.x=fmaf(wm,hv1.x,acc1.x); acc1.y=fmaf(wm,hv1.y,acc1.y);
        acc1.z=fmaf(wm,hv1.z,acc1.z); acc1.w=fmaf(wm,hv1.w,acc1.w);
    }
    float z0 = __shfl_sync(0xffffffffu, z, 0), z1 = __shfl_sync(0xffffffffu, z, 1);
    float z2 = __shfl_sync(0xffffffffu, z, 2), z3 = __shfl_sync(0xffffffffu, z, 3);
    float zm = (myh==0)?z0:(myh==1)?z1:(myh==2)?z2:z3;
    float inv = 1.0f / (zm + 1e-9f);
    acc0.x*=inv; acc0.y*=inv; acc0.z*=inv; acc0.w*=inv;
    acc1.x*=inv; acc1.y*=inv; acc1.z*=inv; acc1.w*=inv;
    float4* op = (float4*)(xg + (size_t)node * HID_ + lane * 8);
    op[0] = acc0; op[1] = acc1;
}

__global__ void pack_support(const float* __restrict__ xg, const float* __restrict__ h0,
                             float* __restrict__ sup)
{
    int i = blockIdx.x * blockDim.x + threadIdx.x;
    if (i >= N_ * 512) return;
    int r = i >> 9, c = i & 511;
    sup[i] = (c < 256) ? xg[(size_t)r*256 + c] : h0[(size_t)r*256 + (c-256)];
}

__global__ void yhat_k(const float* __restrict__ x, const float* __restrict__ W,
                       const float* __restrict__ b)
{
    int i = blockIdx.x * blockDim.x + threadIdx.x;
    if (i >= N_) return;
    const float* r = x + (size_t)i * HID_;
    float l0 = b[0], l1 = b[1];
#pragma unroll 8
    for (int d = 0; d < HID_; d++) {
        float v = r[d];
        l0 = fmaf(v, W[2*d+0], l0);
        l1 = fmaf(v, W[2*d+1], l1);
    }
    g_y[i] = 1.0f / (1.0f + expf(l0 - l1));
}

__global__ void cls_k(const float* __restrict__ x, const float* __restrict__ W,
                      const float* __restrict__ b, float* __restrict__ out)
{
    int i = blockIdx.x * blockDim.x + threadIdx.x;
    if (i >= N_) return;
    const float* r = x + (size_t)i * HID_;
    float l0 = b[0], l1 = b[1];
#pragma unroll 8
    for (int d = 0; d < HID_; d++) {
        float v = r[d];
        l0 = fmaf(v, W[2*d+0], l0);
        l1 = fmaf(v, W[2*d+1], l1);
    }
    out[2*i+0] = l0;
    out[2*i+1] = l1;
}

// ---------------- host orchestration ----------------
extern "C" void kernel_launch(void* const* d_in, const int* in_sizes, int n_in,
                              void* d_out, int out_size)
{
    const float* feat   = (const float*)d_in[0];
    const float* xyz_in = (const float*)d_in[1];
    const int*   src    = (const int*)  d_in[2];
    const int*   dst    = (const int*)  d_in[3];
    const void*  dmask  = d_in[4];
    const void*  bmask  = d_in[5];
    const float* fcW  = (const float*)d_in[6];
    const float* fcb  = (const float*)d_in[7];
    const float* gatW = (const float*)d_in[8];
    const float* al   = (const float*)d_in[9];
    const float* ar   = (const float*)d_in[10];
    const float* gcW  = (const float*)d_in[11];
    const float* cgW  = (const float*)d_in[12];
    const float* cgb  = (const float*)d_in[13];
    const float* qW   = (const float*)d_in[14];
    const float* qb   = (const float*)d_in[15];
    const float* kW   = (const float*)d_in[16];
    const float* kb   = (const float*)d_in[17];
    const float* vW   = (const float*)d_in[18];
    const float* vb   = (const float*)d_in[19];
    const float* oW   = (const float*)d_in[20];
    const float* ob   = (const float*)d_in[21];
    const float* clsW = (const float*)d_in[22];
    const float* clsb = (const float*)d_in[23];

    float *px, *ph0, *phl, *pxg, *psup, *pq, *pk, *pv, *phms, *pS, *pxyz0, *pxyz1;
    float *pxs, *pys, *pzs, *ppart;
    cudaGetSymbolAddress((void**)&px,    g_x);
    cudaGetSymbolAddress((void**)&ph0,   g_h0);
    cudaGetSymbolAddress((void**)&phl,   g_hl);
    cudaGetSymbolAddress((void**)&pxg,   g_xg);
    cudaGetSymbolAddress((void**)&psup,  g_sup);
    cudaGetSymbolAddress((void**)&pq,    g_q);
    cudaGetSymbolAddress((void**)&pk,    g_k);
    cudaGetSymbolAddress((void**)&pv,    g_v);
    cudaGetSymbolAddress((void**)&phms,  g_hms);
    cudaGetSymbolAddress((void**)&pS,    g_S);
    cudaGetSymbolAddress((void**)&pxyz0, g_xyz0);
    cudaGetSymbolAddress((void**)&pxyz1, g_xyz1);
    cudaGetSymbolAddress((void**)&pxs,   g_xs);
    cudaGetSymbolAddress((void**)&pys,   g_ys);
    cudaGetSymbolAddress((void**)&pzs,   g_zs);
    cudaGetSymbolAddress((void**)&ppart, g_part);

    detect_mask_mode<<<1, 1>>>((const unsigned int*)dmask);

    sgemm64<<<dim3(HID_/64, N_/64), 256>>>(feat, fcW, px, ph0, N_, HID_, FEAT_,
                                           fcb, 1, 1.0f, nullptr,0.f, nullptr,0.f, nullptr,0.f);

    zero_cnt<<<N_/256, 256>>>();
    count_edges<<<E_/256, 256>>>(dst);
    scan4096<<<1, 1024>>>();
    scatter_edges<<<E_/256, 256>>>(src, dst);

    const float ALPHA = 0.1f, LAMDA = 0.5f;
    for (int l = 0; l < 4; l++) {
        sgemm64<<<dim3(HID_/64, N_/64), 256>>>(px, gatW + (size_t)l*HID_*HID_, phl, nullptr,
                                               N_, HID_, HID_, nullptr, 0, 1.0f,
                                               nullptr,0.f, nullptr,0.f, nullptr,0.f);
        compute_elr<<<(N_*4)/256, 256>>>(phl, al + l*4*64, ar + l*4*64);
        gat_aggregate<<<N_/8, 256>>>(phl, pxg);
        pack_support<<<(N_*512)/256, 256>>>(pxg, ph0, psup);
        float theta = fminf(1.0f, logf(LAMDA / (float)(l + 1) + 1.0f));
        sgemm64<<<dim3(HID_/64, N_/64), 256>>>(psup, gcW + (size_t)l*512*HID_, px, nullptr,
                                               N_, HID_, 512, nullptr, 0, theta,
                                               pxg, (1.0f-theta)*(1.0f-ALPHA),
                                               ph0, (1.0f-theta)*ALPHA,
                                               px,  1.0f);
    }

    yhat_k<<<N_/256, 256>>>(px, cgW, cgb);

    const float* xyz_cur = xyz_in;
    float* xyz_buf[2] = { pxyz0, pxyz1 };
    for (int l = 0; l < 4; l++) {
        sgemm64<<<dim3(HID_/64, N_/64), 256>>>(px, qW + (size_t)l*HID_*HID_, pq, nullptr,
                                               N_, HID_, HID_, qb + l*HID_, 0, 1.0f,
                                               nullptr,0.f, nullptr,0.f, nullptr,0.f);
        sgemm64<<<dim3(HID_/64, N_/64), 256>>>(px, kW + (size_t)l*HID_*HID_, pk, nullptr,
                                               N_, HID_, HID_, kb + l*HID_, 0, 1.0f,
                                               nullptr,0.f, nullptr,0.f, nullptr,0.f);
        sgemm64<<<dim3(HID_/64, N_/64), 256>>>(px, vW + (size_t)l*HID_*HID_, pv, nullptr,
                                               N_, HID_, HID_, vb + l*HID_, 0, 1.0f,
                                               nullptr,0.f, nullptr,0.f, nullptr,0.f);
        scores128<<<dim3(N_/128, N_/128), 256>>>(pq, pk, xyz_cur, dmask, bmask, pS);
        xyz2soa<<<N_/256, 256>>>(xyz_cur, pxs, pys, pzs);
        softmax_xyz<<<N_, 256>>>(pS, pxs, pys, pzs, xyz_buf[l & 1]);
        sgemm128_splitk<<<dim3(HID_/128, N_/128, KCHUNKS_), 256>>>(pS, pv, ppart, N_, HID_, N_);
        combine_parts<<<(N_*HID_/4)/256, 256>>>(ppart, phms);
        sgemm64<<<dim3(HID_/64, N_/64), 256>>>(phms, oW + (size_t)l*HID_*HID_, px, nullptr,
                                               N_, HID_, HID_, ob + l*HID_, 0, 1.0f,
                                               px, 1.0f, nullptr,0.f, nullptr,0.f);
        xyz_cur = xyz_buf[l & 1];
    }

    cls_k<<<N_/256, 256>>>(px, clsW, clsb, (float*)d_out);
}